// round 11
// baseline (speedup 1.0000x reference)
#include <cuda_runtime.h>
#include <cuda_fp16.h>
#include <cstdint>

#define T_DIM 4096
#define NUM_TILES 2048
#define THREADS 256

// ---- shared memory layout (bytes) ----
// VF: v_tp fp16, K-permuted fragment pack: [ksg(16)][j(8)][lane(32)][16B = nb-even 8B | nb-odd 8B]
#define VF_OFF 0
#define W_OFF  65536
#define SC_OFF 66048
#define SMEM_BYTES 66560

__device__ __forceinline__ uint32_t pack2h(float lo, float hi) {
    uint32_t r;
    asm("cvt.rn.f16x2.f32 %0, %1, %2;" : "=r"(r) : "f"(hi), "f"(lo));
    return r;
}

__device__ __forceinline__ float tanh_fast(float x) {
    float r;
    asm("tanh.approx.f32 %0, %1;" : "=f"(r) : "f"(x));
    return r;
}

__device__ __forceinline__ void sts64(uint32_t addr, uint32_t a, uint32_t b) {
    asm volatile("st.shared.v2.b32 [%0], {%1,%2};" :: "r"(addr), "r"(a), "r"(b) : "memory");
}

__device__ __forceinline__ void lds128(uint32_t* r, uint32_t addr) {
    asm volatile("ld.shared.v4.b32 {%0,%1,%2,%3}, [%4];"
                 : "=r"(r[0]), "=r"(r[1]), "=r"(r[2]), "=r"(r[3]) : "r"(addr));
}

__device__ __forceinline__ void mma16(float* c, const uint32_t* a, uint32_t b0, uint32_t b1) {
    asm volatile(
        "mma.sync.aligned.m16n8k16.row.col.f32.f16.f16.f32 "
        "{%0,%1,%2,%3}, {%4,%5,%6,%7}, {%8,%9}, {%0,%1,%2,%3};\n"
        : "+f"(c[0]), "+f"(c[1]), "+f"(c[2]), "+f"(c[3])
        : "r"(a[0]), "r"(a[1]), "r"(a[2]), "r"(a[3]), "r"(b0), "r"(b1));
}

// Load this lane's 4 A-fragments' raw fp32 for k-slice ks:
// rows r0 (+0,+4,+8,+12 in M-row units = gr +0,+8,+16,+24), 16B each at k = ks*16 + 4*tig.
__device__ __forceinline__ void ldgA(float4* r, const float* hp, int r0, int ks, int tig) {
    const float4* p = (const float4*)(hp + (size_t)r0 * 256) + ks * 4 + tig;
    r[0] = __ldg(p);
    r[1] = __ldg(p + 4 * 64);    // +4 M-rows (gr + 8)
    r[2] = __ldg(p + 8 * 64);    // mt=1 (gr + 16)
    r[3] = __ldg(p + 12 * 64);
}

__global__ void __launch_bounds__(THREADS, 2)
topo_attention_v5(const float* __restrict__ h1,
                  const float* __restrict__ h2,
                  const float* __restrict__ w,
                  const float* __restrict__ v,
                  float* __restrict__ out) {
    extern __shared__ char smem[];
    uint32_t smem_u32;
    asm("{ .reg .u64 t; cvta.to.shared.u64 t, %1; cvt.u32.u64 %0, t; }"
        : "=r"(smem_u32) : "l"(smem));
    float* w_s  = (float*)(smem + W_OFF);
    float* sc_s = (float*)(smem + SC_OFF);

    const int tid  = threadIdx.x;
    const int wid  = tid >> 5;
    const int lane = tid & 31;
    const int warp_m = wid >> 1;    // 4 groups of m32
    const int warp_n = wid & 1;     // 2 groups of n64
    const int g   = lane >> 2;
    const int tig = lane & 3;
    const int bx = blockIdx.x;
    const int grid = gridDim.x;

    // ---- prologue: pack v_tp (fp16, K-permuted fragment layout), load w, zero sc ----
    // Physical k within each 16-group maps to mma slots: phys 4t..4t+3 -> slots {2t,2t+1,2t+8,2t+9}.
    for (int i = tid * 4; i < 32768; i += THREADS * 4) {
        float4 vv = *(const float4*)(v + i);
        int l = i >> 8, m = i & 255;
        int ksg = m >> 4, tp = (m >> 2) & 3;
        int nb = l >> 3, gp = l & 7;
        uint32_t addr = smem_u32 + VF_OFF +
            (uint32_t)(ksg * 4096 + (nb >> 1) * 512 + (gp * 4 + tp) * 16 + (nb & 1) * 8);
        sts64(addr, pack2h(vv.x, vv.y), pack2h(vv.z, vv.w));
    }
    if (tid < 128) { w_s[tid] = w[tid]; sc_s[tid] = 0.0f; }
    __syncthreads();

    // this lane's stream pointer (gr parity == g parity) and B base
    const float* hp = (g & 1) ? h2 : h1;
    const uint32_t vb = smem_u32 + VF_OFF + (uint32_t)(warp_n * 2048 + lane * 16);

    float acc[2][8][4];
    #pragma unroll
    for (int mt = 0; mt < 2; mt++)
        #pragma unroll
        for (int nt = 0; nt < 8; nt++)
            #pragma unroll
            for (int i = 0; i < 4; i++) acc[mt][nt][i] = 0.0f;

    for (int tile = bx; tile < NUM_TILES; tile += grid) {
        // M-row base for this lane: gr0 = tile*128 + warp_m*32 + g ; r0 = gr0 >> 1
        const int r0 = tile * 64 + warp_m * 16 + (g >> 1);

        float4 rgN[4];
        ldgA(rgN, hp, r0, 0, tig);

        #pragma unroll 4
        for (int ks = 0; ks < 16; ++ks) {
            uint32_t afr[2][4];
            #pragma unroll
            for (int mt = 0; mt < 2; ++mt) {
                afr[mt][0] = pack2h(rgN[2 * mt].x,     rgN[2 * mt].y);
                afr[mt][1] = pack2h(rgN[2 * mt + 1].x, rgN[2 * mt + 1].y);
                afr[mt][2] = pack2h(rgN[2 * mt].z,     rgN[2 * mt].w);
                afr[mt][3] = pack2h(rgN[2 * mt + 1].z, rgN[2 * mt + 1].w);
            }
            if (ks < 15) ldgA(rgN, hp, r0, ks + 1, tig);

            const uint32_t va = vb + (uint32_t)(ks * 4096);
            #pragma unroll
            for (int jj = 0; jj < 4; ++jj) {
                uint32_t bb[4];
                lds128(bb, va + (uint32_t)(jj * 512));
                mma16(acc[0][jj * 2],     afr[0], bb[0], bb[1]);
                mma16(acc[0][jj * 2 + 1], afr[0], bb[2], bb[3]);
                mma16(acc[1][jj * 2],     afr[1], bb[0], bb[1]);
                mma16(acc[1][jj * 2 + 1], afr[1], bb[2], bb[3]);
            }
        }

        // ---- epilogue: tanh, w-dot, reduce, 2-way softmax ----
        float part[4];
        #pragma unroll
        for (int mt = 0; mt < 2; ++mt) {
            float p0 = 0.f, p1 = 0.f;
            #pragma unroll
            for (int nt = 0; nt < 8; ++nt) {
                int l0 = warp_n * 64 + nt * 8 + tig * 2;
                float w0 = w_s[l0], w1 = w_s[l0 + 1];
                p0 += w0 * tanh_fast(acc[mt][nt][0]) + w1 * tanh_fast(acc[mt][nt][1]);
                p1 += w0 * tanh_fast(acc[mt][nt][2]) + w1 * tanh_fast(acc[mt][nt][3]);
                #pragma unroll
                for (int i = 0; i < 4; i++) acc[mt][nt][i] = 0.0f;
            }
            part[mt * 2] = p0;
            part[mt * 2 + 1] = p1;
        }
        #pragma unroll
        for (int i = 0; i < 4; i++) {
            part[i] += __shfl_xor_sync(0xffffffffu, part[i], 1);
            part[i] += __shfl_xor_sync(0xffffffffu, part[i], 2);
        }
        if (tig == 0) {
            #pragma unroll
            for (int i = 0; i < 4; i++) {
                int row = warp_m * 32 + (i >> 1) * 16 + (i & 1) * 8 + g;
                atomicAdd(&sc_s[row], part[i]);
            }
        }
        __syncthreads();   // all atomicAdds visible
        if (tid < 64) {
            float s0 = sc_s[2 * tid];
            float s1 = sc_s[2 * tid + 1];
            sc_s[2 * tid] = 0.0f;
            sc_s[2 * tid + 1] = 0.0f;
            int P = tile * 64 + tid;            // global (b*T + t)
            int b = P >> 12;
            int t = P & 4095;
            float a0 = 1.0f / (1.0f + __expf(s1 - s0));
            out[((b * 2) + 0) * T_DIM + t] = a0;
            out[((b * 2) + 1) * T_DIM + t] = 1.0f - a0;
        }
        __syncthreads();   // sc_s re-zero visible before next tile's atomics
    }
}

extern "C" void kernel_launch(void* const* d_in, const int* in_sizes, int n_in,
                              void* d_out, int out_size) {
    const float* h1 = (const float*)d_in[0];
    const float* h2 = (const float*)d_in[1];
    const float* w  = (const float*)d_in[2];
    const float* v  = (const float*)d_in[3];
    float* out = (float*)d_out;

    cudaFuncSetAttribute(topo_attention_v5,
                         cudaFuncAttributeMaxDynamicSharedMemorySize, SMEM_BYTES);

    int nsm = 148;
    if (cudaDeviceGetAttribute(&nsm, cudaDevAttrMultiProcessorCount, 0) != cudaSuccess || nsm <= 0)
        nsm = 148;

    topo_attention_v5<<<2 * nsm, THREADS, SMEM_BYTES>>>(h1, h2, w, v, out);
}